// round 2
// baseline (speedup 1.0000x reference)
#include <cuda_runtime.h>

// Problem constants
#define BATCH   4
#define NPTS    16384
#define HALF    8192
#define FDIM    32
#define GD      32               // grid cells per axis
#define NC      (GD*GD*GD)       // 32768 cells

// Output layout (concatenated tuple, float32)
#define OFF_VPC   0
#define OFF_VFEAT (BATCH * HALF * 3)                  // 98304
#define OFF_NIDX  (OFF_VFEAT + BATCH * HALF * FDIM)   // 1146880
#define OFF_RNDS  (OFF_NIDX + BATCH * HALF)           // 1179648

// ---------------------------------------------------------------------------
// Scratch (device globals; no allocation allowed)
// ---------------------------------------------------------------------------
__device__ float4   g_valid[BATCH][HALF];   // (2x, 2y, 2z, p2) original order
__device__ float4   g_query[BATCH][HALF];   // (x, y, z, q2)  original order
__device__ unsigned g_bbox[6];              // encoded min x/y/z, max x/y/z
__device__ float    g_grid[12];             // [0..2] origin, [3..5] scale, [6..8] cellsize, [9] cellmin
__device__ int      g_cnt[2][BATCH][NC];    // histograms: kind 0 = points, 1 = queries
__device__ int      g_off[2][BATCH][NC+1];  // exclusive offsets
__device__ int      g_cur[2][BATCH][NC];    // scatter cursors
__device__ float4   g_spt[BATCH][HALF];     // cell-sorted points (2x,2y,2z,p2)
__device__ int      g_sid[BATCH][HALF];     // original point index
__device__ float4   g_sq[BATCH][HALF];      // cell-sorted queries (x,y,z,q2)
__device__ int      g_sqid[BATCH][HALF];    // original query index

// Order-preserving float<->uint encode for atomicMin/Max bbox
__device__ __forceinline__ unsigned fenc(float f) {
    unsigned u = __float_as_uint(f);
    return (u & 0x80000000u) ? ~u : (u | 0x80000000u);
}
__device__ __forceinline__ float fdec(unsigned k) {
    unsigned u = (k & 0x80000000u) ? (k ^ 0x80000000u) : ~k;
    return __uint_as_float(u);
}

// ||v||^2 left-to-right, no FMA contraction (match jax fp32 semantics)
__device__ __forceinline__ float sq3(float x, float y, float z) {
    return __fadd_rn(__fadd_rn(__fmul_rn(x, x), __fmul_rn(y, y)), __fmul_rn(z, z));
}

// ---------------------------------------------------------------------------
// K0: zero histograms + reset bbox (must run every launch; graph replays)
// ---------------------------------------------------------------------------
__global__ void init_kernel() {
    int i = blockIdx.x * blockDim.x + threadIdx.x;
    if (i < 2 * BATCH * NC) ((int*)g_cnt)[i] = 0;
    if (i < 3) g_bbox[i] = 0xFFFFFFFFu;      // min slots
    else if (i < 6) g_bbox[i] = 0u;          // max slots
}

// ---------------------------------------------------------------------------
// K1: gathers (valid_feats, valid_pc->out+scratch, invalid_pc->scratch, rnds)
//     + bbox reduction over valid points
// ---------------------------------------------------------------------------
__global__ void gather_kernel(const float* __restrict__ pc,
                              const float4* __restrict__ feats4,
                              const int* __restrict__ rnds,
                              float* __restrict__ out) {
    int gi = blockIdx.x * blockDim.x + threadIdx.x;
    const int WF = BATCH * HALF * 8;
    const int WP = BATCH * HALF;

    unsigned kmin[3] = {0xFFFFFFFFu, 0xFFFFFFFFu, 0xFFFFFFFFu};
    unsigned kmax[3] = {0u, 0u, 0u};

    int i = gi;
    if (i < WF) {
        int c = i & 7;
        int t = (i >> 3) & (HALF - 1);
        int b = i >> 16;
        int v = rnds[t];
        float4 val = feats4[(b * NPTS + v) * 8 + c];
        ((float4*)(out + OFF_VFEAT))[(b * HALF + t) * 8 + c] = val;
    } else {
        i -= WF;
        if (i < WP) {
            int t = i & (HALF - 1);
            int b = i >> 13;
            int v = rnds[t];
            int base = (b * NPTS + v) * 3;
            float x = pc[base + 0], y = pc[base + 1], z = pc[base + 2];
            int ob = OFF_VPC + (b * HALF + t) * 3;
            out[ob + 0] = x; out[ob + 1] = y; out[ob + 2] = z;
            g_valid[b][t] = make_float4(2.0f * x, 2.0f * y, 2.0f * z, sq3(x, y, z));
            kmin[0] = kmax[0] = fenc(x);
            kmin[1] = kmax[1] = fenc(y);
            kmin[2] = kmax[2] = fenc(z);
        } else {
            i -= WP;
            if (i < WP) {
                int t = i & (HALF - 1);
                int b = i >> 13;
                int v = rnds[HALF + t];
                int base = (b * NPTS + v) * 3;
                float x = pc[base + 0], y = pc[base + 1], z = pc[base + 2];
                g_query[b][t] = make_float4(x, y, z, sq3(x, y, z));
            } else {
                i -= WP;
                if (i < NPTS) out[OFF_RNDS + i] = (float)rnds[i];
            }
        }
    }

    // Block-level bbox reduction (full blocks: total threads == 1344*256 exactly)
    __shared__ unsigned sbb[6];
    if (threadIdx.x < 3) sbb[threadIdx.x] = 0xFFFFFFFFu;
    else if (threadIdx.x < 6) sbb[threadIdx.x] = 0u;
    __syncthreads();
#pragma unroll
    for (int c = 0; c < 3; ++c) {
        unsigned wmin = __reduce_min_sync(0xFFFFFFFFu, kmin[c]);
        unsigned wmax = __reduce_max_sync(0xFFFFFFFFu, kmax[c]);
        if ((threadIdx.x & 31) == 0) {
            atomicMin(&sbb[c], wmin);
            atomicMax(&sbb[3 + c], wmax);
        }
    }
    __syncthreads();
    if (threadIdx.x < 3) atomicMin(&g_bbox[threadIdx.x], sbb[threadIdx.x]);
    else if (threadIdx.x < 6) atomicMax(&g_bbox[threadIdx.x], sbb[threadIdx.x]);
}

// ---------------------------------------------------------------------------
// K2: grid parameters from bbox (1 thread)
// ---------------------------------------------------------------------------
__global__ void setup_kernel() {
    if (threadIdx.x == 0 && blockIdx.x == 0) {
        float cmin = 3.4e38f;
#pragma unroll
        for (int c = 0; c < 3; ++c) {
            float mn = fdec(g_bbox[c]);
            float mx = fdec(g_bbox[3 + c]);
            float r = mx - mn;
            float scale = (float)GD / (r * (1.0f + 1e-5f) + 1e-20f);
            float cs = 1.0f / scale;
            g_grid[c] = mn;
            g_grid[3 + c] = scale;
            g_grid[6 + c] = cs;
            cmin = fminf(cmin, cs);
        }
        g_grid[9] = cmin;
    }
}

// ---------------------------------------------------------------------------
// K3: histogram points + queries into cells
// ---------------------------------------------------------------------------
__device__ __forceinline__ int cell_of(float x, float y, float z,
                                       float ox, float oy, float oz,
                                       float sx, float sy, float sz) {
    int cx = (int)((x - ox) * sx); cx = max(0, min(GD - 1, cx));
    int cy = (int)((y - oy) * sy); cy = max(0, min(GD - 1, cy));
    int cz = (int)((z - oz) * sz); cz = max(0, min(GD - 1, cz));
    return (cz * GD + cy) * GD + cx;
}

__global__ void count_kernel() {
    int i = blockIdx.x * blockDim.x + threadIdx.x;
    if (i >= 2 * BATCH * HALF) return;
    int kind = i >> 15;
    int b = (i >> 13) & (BATCH - 1);
    int t = i & (HALF - 1);
    float ox = g_grid[0], oy = g_grid[1], oz = g_grid[2];
    float sx = g_grid[3], sy = g_grid[4], sz = g_grid[5];
    float x, y, z;
    if (kind == 0) {
        float4 f = g_valid[b][t];
        x = 0.5f * f.x; y = 0.5f * f.y; z = 0.5f * f.z;
    } else {
        float4 f = g_query[b][t];
        x = f.x; y = f.y; z = f.z;
    }
    int cid = cell_of(x, y, z, ox, oy, oz, sx, sy, sz);
    atomicAdd(&g_cnt[kind][b][cid], 1);
}

// ---------------------------------------------------------------------------
// K4: exclusive scan of 32768 cells per (kind, batch); 8 blocks x 1024 thr
// ---------------------------------------------------------------------------
__global__ void __launch_bounds__(1024) scan_kernel() {
    int kind = blockIdx.x >> 2;
    int b = blockIdx.x & 3;
    const int CPT = NC / 1024;  // 32 cells per thread
    int tid = threadIdx.x;

    int loc[CPT];
    int s = 0;
    const int* cnt = g_cnt[kind][b];
#pragma unroll
    for (int j = 0; j < CPT; ++j) {
        loc[j] = s;
        s += cnt[tid * CPT + j];
    }

    __shared__ int sh[1024];
    sh[tid] = s;
    __syncthreads();
    // Hillis-Steele inclusive scan
    for (int off = 1; off < 1024; off <<= 1) {
        int v = (tid >= off) ? sh[tid - off] : 0;
        __syncthreads();
        sh[tid] += v;
        __syncthreads();
    }
    int base = (tid > 0) ? sh[tid - 1] : 0;

    int* off_arr = g_off[kind][b];
    int* cur_arr = g_cur[kind][b];
#pragma unroll
    for (int j = 0; j < CPT; ++j) {
        int v = base + loc[j];
        off_arr[tid * CPT + j] = v;
        cur_arr[tid * CPT + j] = v;
    }
    if (tid == 1023) off_arr[NC] = sh[1023];
}

// ---------------------------------------------------------------------------
// K5: scatter points/queries into cell-sorted order
// ---------------------------------------------------------------------------
__global__ void scatter_kernel() {
    int i = blockIdx.x * blockDim.x + threadIdx.x;
    if (i >= 2 * BATCH * HALF) return;
    int kind = i >> 15;
    int b = (i >> 13) & (BATCH - 1);
    int t = i & (HALF - 1);
    float ox = g_grid[0], oy = g_grid[1], oz = g_grid[2];
    float sx = g_grid[3], sy = g_grid[4], sz = g_grid[5];
    if (kind == 0) {
        float4 f = g_valid[b][t];
        int cid = cell_of(0.5f * f.x, 0.5f * f.y, 0.5f * f.z, ox, oy, oz, sx, sy, sz);
        int pos = atomicAdd(&g_cur[0][b][cid], 1);
        g_spt[b][pos] = f;
        g_sid[b][pos] = t;
    } else {
        float4 f = g_query[b][t];
        int cid = cell_of(f.x, f.y, f.z, ox, oy, oz, sx, sy, sz);
        int pos = atomicAdd(&g_cur[1][b][cid], 1);
        g_sq[b][pos] = f;
        g_sqid[b][pos] = t;
    }
}

// ---------------------------------------------------------------------------
// K6: grid KNN. One thread per (sorted) query. Expanding Chebyshev shells,
// exact per-cell box-distance pruning with conservative margins, exact
// reference-rounding distance on every examined candidate, tie-break by
// original index (order-independent & superset-safe => bit-identical result).
// ---------------------------------------------------------------------------
__global__ void __launch_bounds__(256) knn_kernel(float* __restrict__ out) {
    int i = blockIdx.x * blockDim.x + threadIdx.x;
    int b = i >> 13;
    int s = i & (HALF - 1);

    float4 q = g_sq[b][s];
    int qi = g_sqid[b][s];
    const float qx = q.x, qy = q.y, qz = q.z, q2 = q.w;

    float ox = g_grid[0], oy = g_grid[1], oz = g_grid[2];
    float sx = g_grid[3], sy = g_grid[4], sz = g_grid[5];
    float cx = g_grid[6], cy = g_grid[7], cz = g_grid[8];
    float cellmin = g_grid[9];
    // margins: expand cell boxes slightly (covers binning fp slop)
    float mgx = cx * 1e-3f, mgy = cy * 1e-3f, mgz = cz * 1e-3f;

    int qcx = (int)((qx - ox) * sx); qcx = max(0, min(GD - 1, qcx));
    int qcy = (int)((qy - oy) * sy); qcy = max(0, min(GD - 1, qcy));
    int qcz = (int)((qz - oz) * sz); qcz = max(0, min(GD - 1, qcz));

    const float INF = __int_as_float(0x7f800000);
    float bd1 = INF, bd2 = INF;
    int bi1 = 0x7fffffff, bi2 = 0x7fffffff;

    const int* offs = g_off[0][b];
    const float4* pts = g_spt[b];
    const int* ids = g_sid[b];

    for (int r = 0; r < GD; ++r) {
        int x0 = max(qcx - r, 0), x1 = min(qcx + r, GD - 1);
        int y0 = max(qcy - r, 0), y1 = min(qcy + r, GD - 1);
        int z0 = max(qcz - r, 0), z1 = min(qcz + r, GD - 1);
        for (int gz = z0; gz <= z1; ++gz) {
            bool ez = (gz == qcz - r) || (gz == qcz + r);
            for (int gy = y0; gy <= y1; ++gy) {
                bool ey = (gy == qcy - r) || (gy == qcy + r);
                for (int gx = x0; gx <= x1; ++gx) {
                    if (!(ez || ey || gx == qcx - r || gx == qcx + r)) continue;
                    // conservative min distance^2 from query to cell box
                    float lx = ox + gx * cx - mgx, hx = ox + (gx + 1) * cx + mgx;
                    float ly = oy + gy * cy - mgy, hy = oy + (gy + 1) * cy + mgy;
                    float lz = oz + gz * cz - mgz, hz = oz + (gz + 1) * cz + mgz;
                    float dx = qx - fminf(fmaxf(qx, lx), hx);
                    float dy = qy - fminf(fmaxf(qy, ly), hy);
                    float dz = qz - fminf(fmaxf(qz, lz), hz);
                    float d2b = dx * dx + dy * dy + dz * dz;
                    if (d2b > bd2 * 1.001f + 1e-5f) continue;

                    int cid = (gz * GD + gy) * GD + gx;
                    int p0 = offs[cid], p1 = offs[cid + 1];
                    for (int p = p0; p < p1; ++p) {
                        float4 P = pts[p];
                        float dot2 = __fadd_rn(__fadd_rn(__fmul_rn(qx, P.x),
                                                         __fmul_rn(qy, P.y)),
                                               __fmul_rn(qz, P.z));
                        float d2 = __fsub_rn(__fadd_rn(q2, P.w), dot2);
                        int id = ids[p];
                        if (d2 < bd1 || (d2 == bd1 && id < bi1)) {
                            bd2 = bd1; bi2 = bi1; bd1 = d2; bi1 = id;
                        } else if (d2 < bd2 || (d2 == bd2 && id < bi2)) {
                            bd2 = d2; bi2 = id;
                        }
                    }
                }
            }
        }
        // cells not yet visited have Chebyshev dist >= r+1 => dist >= r*cellmin
        if (bd2 < INF) {
            float lb = (float)r * cellmin * 0.999f;
            if (lb * lb > bd2 * 1.001f + 1e-5f) break;
        }
    }

    out[OFF_NIDX + (b << 13) + qi] = (float)bi2;
}

// ---------------------------------------------------------------------------
extern "C" void kernel_launch(void* const* d_in, const int* in_sizes, int n_in,
                              void* d_out, int out_size) {
    const float*  pc    = (const float*)d_in[0];
    const float4* feats = (const float4*)d_in[1];
    const int*    rnds  = (const int*)d_in[2];
    float*        out   = (float*)d_out;
    (void)in_sizes; (void)n_in; (void)out_size;

    init_kernel<<<(2 * BATCH * NC + 255) / 256, 256>>>();

    const int total = BATCH * HALF * 8 + 2 * BATCH * HALF + NPTS;  // 344064
    gather_kernel<<<total / 256, 256>>>(pc, feats, rnds, out);

    setup_kernel<<<1, 32>>>();
    count_kernel<<<(2 * BATCH * HALF + 255) / 256, 256>>>();
    scan_kernel<<<2 * BATCH, 1024>>>();
    scatter_kernel<<<(2 * BATCH * HALF + 255) / 256, 256>>>();
    knn_kernel<<<(BATCH * HALF + 255) / 256, 256>>>(out);
}

// round 4
// speedup vs baseline: 1.1349x; 1.1349x over previous
#include <cuda_runtime.h>

// Problem constants
#define BATCH   4
#define NPTS    16384
#define HALF    8192
#define FDIM    32
#define GD      16               // cells per axis (in CDF/u-space)
#define NC      (GD*GD*GD)       // 4096 cells per batch

// Output layout (concatenated tuple, float32)
#define OFF_VPC   0
#define OFF_VFEAT (BATCH * HALF * 3)                  // 98304
#define OFF_NIDX  (OFF_VFEAT + BATCH * HALF * FDIM)   // 1146880
#define OFF_RNDS  (OFF_NIDX + BATCH * HALF)           // 1179648

// Cell boundaries in x-space: standard normal quantiles Phi^-1(i/16).
// Data is N(0,1) per axis => uniform occupancy across cells. Correctness does
// NOT depend on this (pruning is geometric & conservative) — only balance does.
__constant__ float c_bnd[GD + 1] = {
    -1e30f,
    -1.5341206f, -1.1503494f, -0.8871466f, -0.6744898f,
    -0.4887764f, -0.3186394f, -0.1573107f,  0.0f,
     0.1573107f,  0.3186394f,  0.4887764f,  0.6744898f,
     0.8871466f,  1.1503494f,  1.5341206f,
     1e30f
};

// ---------------------------------------------------------------------------
// Scratch (device globals; no allocation allowed)
// ---------------------------------------------------------------------------
__device__ float4 g_valid[BATCH][HALF];   // (2x, 2y, 2z, p2) original order
__device__ float4 g_query[BATCH][HALF];   // (x, y, z, q2)  original order
__device__ int    g_pcell[BATCH][HALF];   // point cell id
__device__ int    g_qcell[BATCH][HALF];   // query cell id
__device__ int    g_cnt[2][BATCH][NC];    // histograms: 0 = points, 1 = queries
__device__ int    g_off[2][BATCH][NC+1];  // exclusive offsets
__device__ int    g_cur[2][BATCH][NC];    // scatter cursors
__device__ float4 g_spt[BATCH][HALF];     // cell-sorted points (2x,2y,2z,p2)
__device__ int    g_sid[BATCH][HALF];     // original point index
__device__ float4 g_sq[BATCH][HALF];      // cell-sorted queries (x,y,z,q2)
__device__ int    g_sqid[BATCH][HALF];    // original query index

// ||v||^2 left-to-right, no FMA contraction (match jax fp32 semantics)
__device__ __forceinline__ float sq3(float x, float y, float z) {
    return __fadd_rn(__fadd_rn(__fmul_rn(x, x), __fmul_rn(y, y)), __fmul_rn(z, z));
}

// CDF-space axis cell: u = Phi(x) = 0.5*(1+erf(x/sqrt(2))), cell = floor(u*GD)
__device__ __forceinline__ int axis_cell(float x) {
    float u = __fmaf_rn(erff(x * 0.70710678f), 0.5f, 0.5f);
    int c = (int)(u * (float)GD);
    return max(0, min(GD - 1, c));
}
__device__ __forceinline__ int cell_of(float x, float y, float z) {
    return (axis_cell(z) * GD + axis_cell(y)) * GD + axis_cell(x);
}

// ---------------------------------------------------------------------------
// K0: zero histograms (graph replays => must reset every launch)
// ---------------------------------------------------------------------------
__global__ void init_kernel() {
    int i = blockIdx.x * blockDim.x + threadIdx.x;
    if (i < 2 * BATCH * NC) ((int*)g_cnt)[i] = 0;
}

// ---------------------------------------------------------------------------
// K1: gathers + binning + histogram.
//   [0, WF)      : valid_feats as float4
//   [WF, +WP)    : valid_pc -> out + scratch, bin, count
//   [.., +WP)    : invalid_pc -> query scratch, bin, count
//   [.., +NPTS)  : rnds -> out
// ---------------------------------------------------------------------------
__global__ void gather_kernel(const float* __restrict__ pc,
                              const float4* __restrict__ feats4,
                              const int* __restrict__ rnds,
                              float* __restrict__ out) {
    int i = blockIdx.x * blockDim.x + threadIdx.x;
    const int WF = BATCH * HALF * 8;
    const int WP = BATCH * HALF;

    if (i < WF) {
        int c = i & 7;
        int t = (i >> 3) & (HALF - 1);
        int b = i >> 16;
        int v = rnds[t];
        float4 val = feats4[(b * NPTS + v) * 8 + c];
        ((float4*)(out + OFF_VFEAT))[(b * HALF + t) * 8 + c] = val;
        return;
    }
    i -= WF;
    if (i < WP) {
        int t = i & (HALF - 1);
        int b = i >> 13;
        int v = rnds[t];
        int base = (b * NPTS + v) * 3;
        float x = pc[base + 0], y = pc[base + 1], z = pc[base + 2];
        int ob = OFF_VPC + (b * HALF + t) * 3;
        out[ob + 0] = x; out[ob + 1] = y; out[ob + 2] = z;
        g_valid[b][t] = make_float4(2.0f * x, 2.0f * y, 2.0f * z, sq3(x, y, z));
        int cid = cell_of(x, y, z);
        g_pcell[b][t] = cid;
        atomicAdd(&g_cnt[0][b][cid], 1);
        return;
    }
    i -= WP;
    if (i < WP) {
        int t = i & (HALF - 1);
        int b = i >> 13;
        int v = rnds[HALF + t];
        int base = (b * NPTS + v) * 3;
        float x = pc[base + 0], y = pc[base + 1], z = pc[base + 2];
        g_query[b][t] = make_float4(x, y, z, sq3(x, y, z));
        int cid = cell_of(x, y, z);
        g_qcell[b][t] = cid;
        atomicAdd(&g_cnt[1][b][cid], 1);
        return;
    }
    i -= WP;
    if (i < NPTS) out[OFF_RNDS + i] = (float)rnds[i];
}

// ---------------------------------------------------------------------------
// K2: exclusive scan of 4096 cells per (kind, batch); 8 blocks x 1024 thr
// ---------------------------------------------------------------------------
__global__ void __launch_bounds__(1024) scan_kernel() {
    int kind = blockIdx.x >> 2;
    int b = blockIdx.x & 3;
    const int CPT = NC / 1024;  // 4 cells per thread
    int tid = threadIdx.x;

    int loc[CPT];
    int s = 0;
    const int* cnt = g_cnt[kind][b];
#pragma unroll
    for (int j = 0; j < CPT; ++j) {
        loc[j] = s;
        s += cnt[tid * CPT + j];
    }

    __shared__ int sh[1024];
    sh[tid] = s;
    __syncthreads();
    for (int off = 1; off < 1024; off <<= 1) {
        int v = (tid >= off) ? sh[tid - off] : 0;
        __syncthreads();
        sh[tid] += v;
        __syncthreads();
    }
    int base = (tid > 0) ? sh[tid - 1] : 0;

    int* off_arr = g_off[kind][b];
    int* cur_arr = g_cur[kind][b];
#pragma unroll
    for (int j = 0; j < CPT; ++j) {
        int v = base + loc[j];
        off_arr[tid * CPT + j] = v;
        cur_arr[tid * CPT + j] = v;
    }
    if (tid == 1023) off_arr[NC] = sh[1023];
}

// ---------------------------------------------------------------------------
// K3: scatter points/queries into cell-sorted order (cells precomputed)
// ---------------------------------------------------------------------------
__global__ void scatter_kernel() {
    int i = blockIdx.x * blockDim.x + threadIdx.x;
    if (i >= 2 * BATCH * HALF) return;
    int kind = i >> 15;
    int b = (i >> 13) & (BATCH - 1);
    int t = i & (HALF - 1);
    if (kind == 0) {
        int cid = g_pcell[b][t];
        int pos = atomicAdd(&g_cur[0][b][cid], 1);
        g_spt[b][pos] = g_valid[b][t];
        g_sid[b][pos] = t;
    } else {
        int cid = g_qcell[b][t];
        int pos = atomicAdd(&g_cur[1][b][cid], 1);
        g_sq[b][pos] = g_query[b][t];
        g_sqid[b][pos] = t;
    }
}

// ---------------------------------------------------------------------------
// K4: grid KNN in CDF-space grid. One thread per (sorted) query.
// Expanding Chebyshev shells in grid space; per-cell box-distance pruning in
// x-space using quantile boundaries (conservative margins); every examined
// candidate scored with the exact reference-rounded formula; tie-break by
// original index => result order-independent and bit-identical to reference.
// ---------------------------------------------------------------------------
__global__ void __launch_bounds__(256) knn_kernel(float* __restrict__ out) {
    __shared__ int   soffs[NC + 1];
    __shared__ float sbnd[GD + 1];

    int i = blockIdx.x * blockDim.x + threadIdx.x;
    int b = i >> 13;
    int s = i & (HALF - 1);

    for (int j = threadIdx.x; j < NC + 1; j += 256) soffs[j] = g_off[0][b][j];
    if (threadIdx.x < GD + 1) sbnd[threadIdx.x] = c_bnd[threadIdx.x];
    __syncthreads();

    float4 q = g_sq[b][s];
    int qi = g_sqid[b][s];
    const float qx = q.x, qy = q.y, qz = q.z, q2 = q.w;

    int qc = g_qcell[b][qi];  // consistent with binning (stored)
    int qcx = qc & (GD - 1);
    int qcy = (qc >> 4) & (GD - 1);
    int qcz = qc >> 8;

    const float INF = __int_as_float(0x7f800000);
    const float MARG = 1e-5f;   // box expansion (covers erf-vs-quantile slop)
    float bd1 = INF, bd2 = INF;
    int bi1 = 0x7fffffff, bi2 = 0x7fffffff;

    const float4* pts = g_spt[b];
    const int* ids = g_sid[b];

    for (int r = 0; r < GD; ++r) {
        int x0 = max(qcx - r, 0), x1 = min(qcx + r, GD - 1);
        int y0 = max(qcy - r, 0), y1 = min(qcy + r, GD - 1);
        int z0 = max(qcz - r, 0), z1 = min(qcz + r, GD - 1);
        for (int gz = z0; gz <= z1; ++gz) {
            bool ez = (gz == qcz - r) || (gz == qcz + r);
            float lz = sbnd[gz] - MARG, hz = sbnd[gz + 1] + MARG;
            float dz = (qz < lz) ? (lz - qz) : ((qz > hz) ? (qz - hz) : 0.0f);
            for (int gy = y0; gy <= y1; ++gy) {
                bool ey = (gy == qcy - r) || (gy == qcy + r);
                float ly = sbnd[gy] - MARG, hy = sbnd[gy + 1] + MARG;
                float dy = (qy < ly) ? (ly - qy) : ((qy > hy) ? (qy - hy) : 0.0f);
                float dyz = dy * dy + dz * dz;
                for (int gx = x0; gx <= x1; ++gx) {
                    if (!(ez || ey || gx == qcx - r || gx == qcx + r)) continue;
                    float lx = sbnd[gx] - MARG, hx = sbnd[gx + 1] + MARG;
                    float dx = (qx < lx) ? (lx - qx) : ((qx > hx) ? (qx - hx) : 0.0f);
                    float d2b = dx * dx + dyz;
                    if (d2b > bd2 * 1.001f + 1e-4f) continue;

                    int cid = (gz * GD + gy) * GD + gx;
                    int p0 = soffs[cid], p1 = soffs[cid + 1];
                    for (int p = p0; p < p1; ++p) {
                        float4 P = pts[p];
                        float dot2 = __fadd_rn(__fadd_rn(__fmul_rn(qx, P.x),
                                                         __fmul_rn(qy, P.y)),
                                               __fmul_rn(qz, P.z));
                        float d2 = __fsub_rn(__fadd_rn(q2, P.w), dot2);
                        int id = ids[p];
                        if (d2 < bd1 || (d2 == bd1 && id < bi1)) {
                            bd2 = bd1; bi2 = bi1; bd1 = d2; bi1 = id;
                        } else if (d2 < bd2 || (d2 == bd2 && id < bi2)) {
                            bd2 = d2; bi2 = id;
                        }
                    }
                }
            }
        }
        // Unvisited cells lie outside box [qc-r, qc+r]: min distance is the
        // nearest of the six bounding faces (INF if box reaches grid edge).
        if (bd2 < INF) {
            float lb = INF;
            if (qcx - r > 0)      lb = fminf(lb, qx - sbnd[qcx - r]);
            if (qcx + r < GD - 1) lb = fminf(lb, sbnd[qcx + r + 1] - qx);
            if (qcy - r > 0)      lb = fminf(lb, qy - sbnd[qcy - r]);
            if (qcy + r < GD - 1) lb = fminf(lb, sbnd[qcy + r + 1] - qy);
            if (qcz - r > 0)      lb = fminf(lb, qz - sbnd[qcz - r]);
            if (qcz + r < GD - 1) lb = fminf(lb, sbnd[qcz + r + 1] - qz);
            float lba = fmaxf(lb - MARG, 0.0f);
            if (lba * lba > bd2 * 1.001f + 1e-4f) break;
        }
    }

    out[OFF_NIDX + (b << 13) + qi] = (float)bi2;
}

// ---------------------------------------------------------------------------
extern "C" void kernel_launch(void* const* d_in, const int* in_sizes, int n_in,
                              void* d_out, int out_size) {
    const float*  pc    = (const float*)d_in[0];
    const float4* feats = (const float4*)d_in[1];
    const int*    rnds  = (const int*)d_in[2];
    float*        out   = (float*)d_out;
    (void)in_sizes; (void)n_in; (void)out_size;

    init_kernel<<<(2 * BATCH * NC + 255) / 256, 256>>>();

    const int total = BATCH * HALF * 8 + 2 * BATCH * HALF + NPTS;  // 344064
    gather_kernel<<<total / 256, 256>>>(pc, feats, rnds, out);

    scan_kernel<<<2 * BATCH, 1024>>>();
    scatter_kernel<<<(2 * BATCH * HALF + 255) / 256, 256>>>();
    knn_kernel<<<(BATCH * HALF + 255) / 256, 256>>>(out);
}

// round 6
// speedup vs baseline: 1.8217x; 1.6052x over previous
#include <cuda_runtime.h>

// Problem constants
#define BATCH   4
#define NPTS    16384
#define HALF    8192
#define FDIM    32
#define GD      16               // cells per axis (in CDF/u-space)
#define NC      (GD*GD*GD)       // 4096 cells per batch

// Output layout (concatenated tuple, float32)
#define OFF_VPC   0
#define OFF_VFEAT (BATCH * HALF * 3)                  // 98304
#define OFF_NIDX  (OFF_VFEAT + BATCH * HALF * FDIM)   // 1146880
#define OFF_RNDS  (OFF_NIDX + BATCH * HALF)           // 1179648

// Cell boundaries in x-space: standard normal quantiles Phi^-1(i/16).
// Data is N(0,1) per axis => ~2 points/cell everywhere. Correctness does NOT
// depend on this (pruning is geometric & conservative) — only balance does.
__constant__ float c_bnd[GD + 1] = {
    -1e30f,
    -1.5341206f, -1.1503494f, -0.8871466f, -0.6744898f,
    -0.4887764f, -0.3186394f, -0.1573107f,  0.0f,
     0.1573107f,  0.3186394f,  0.4887764f,  0.6744898f,
     0.8871466f,  1.1503494f,  1.5341206f,
     1e30f
};

// ---------------------------------------------------------------------------
// Scratch (device globals; no allocation allowed)
// ---------------------------------------------------------------------------
__device__ float4 g_valid[BATCH][HALF];   // (2x, 2y, 2z, p2) original order
__device__ float4 g_query[BATCH][HALF];   // (x, y, z, q2)  original order
__device__ int    g_pcell[BATCH][HALF];   // point cell id
__device__ int    g_qcell[BATCH][HALF];   // query cell id
__device__ int    g_cnt[2][BATCH][NC];    // histograms: 0 = points, 1 = queries
__device__ int    g_off[2][BATCH][NC+1];  // exclusive offsets
__device__ int    g_cur[2][BATCH][NC];    // scatter cursors
__device__ float4 g_spt[BATCH][HALF];     // cell-sorted points (2x,2y,2z,p2)
__device__ int    g_sid[BATCH][HALF];     // original point index
__device__ float4 g_sq[BATCH][HALF];      // cell-sorted queries (x,y,z,q2)
__device__ int    g_sqid[BATCH][HALF];    // original query index
__device__ int    g_sqc[BATCH][HALF];     // cell id of sorted query

// ||v||^2 left-to-right, no FMA contraction (match jax fp32 semantics)
__device__ __forceinline__ float sq3(float x, float y, float z) {
    return __fadd_rn(__fadd_rn(__fmul_rn(x, x), __fmul_rn(y, y)), __fmul_rn(z, z));
}

// CDF-space axis cell: u = Phi(x) = 0.5*(1+erf(x/sqrt(2))), cell = floor(u*GD)
__device__ __forceinline__ int axis_cell(float x) {
    float u = __fmaf_rn(erff(x * 0.70710678f), 0.5f, 0.5f);
    int c = (int)(u * (float)GD);
    return max(0, min(GD - 1, c));
}
__device__ __forceinline__ int cell_of(float x, float y, float z) {
    return (axis_cell(z) * GD + axis_cell(y)) * GD + axis_cell(x);
}

// strict-order comparator matching stable top_k: smaller dist, then smaller idx
__device__ __forceinline__ bool lt2(float d, int i, float e, int j) {
    return d < e || (d == e && i < j);
}

// Insert candidate (d, i) into sorted top-2 state, deduping by id.
// Same id always carries the bit-identical distance (deterministic formula),
// so id-dedup alone is sound. Safe under duplicated lane state.
__device__ __forceinline__ void ins2(float d, int i,
                                     float& bd1, int& bi1,
                                     float& bd2, int& bi2) {
    if (i == bi1 || i == bi2) return;
    if (lt2(d, i, bd1, bi1)) {
        bd2 = bd1; bi2 = bi1; bd1 = d; bi1 = i;
    } else if (lt2(d, i, bd2, bi2)) {
        bd2 = d; bi2 = i;
    }
}

// Warp butterfly top-2 reduction using dedup-safe insertion merge.
__device__ __forceinline__ void warp_reduce_top2(float& bd1, int& bi1,
                                                 float& bd2, int& bi2) {
#pragma unroll
    for (int o = 16; o > 0; o >>= 1) {
        float e1 = __shfl_xor_sync(0xFFFFFFFFu, bd1, o);
        float e2 = __shfl_xor_sync(0xFFFFFFFFu, bd2, o);
        int j1 = __shfl_xor_sync(0xFFFFFFFFu, bi1, o);
        int j2 = __shfl_xor_sync(0xFFFFFFFFu, bi2, o);
        ins2(e1, j1, bd1, bi1, bd2, bi2);
        ins2(e2, j2, bd1, bi1, bd2, bi2);
    }
}

// ---------------------------------------------------------------------------
// K0: zero histograms (graph replays => must reset every launch)
// ---------------------------------------------------------------------------
__global__ void init_kernel() {
    int i = blockIdx.x * blockDim.x + threadIdx.x;
    if (i < 2 * BATCH * NC) ((int*)g_cnt)[i] = 0;
}

// ---------------------------------------------------------------------------
// K1: gathers + binning + histogram
// ---------------------------------------------------------------------------
__global__ void gather_kernel(const float* __restrict__ pc,
                              const float4* __restrict__ feats4,
                              const int* __restrict__ rnds,
                              float* __restrict__ out) {
    int i = blockIdx.x * blockDim.x + threadIdx.x;
    const int WF = BATCH * HALF * 8;
    const int WP = BATCH * HALF;

    if (i < WF) {
        int c = i & 7;
        int t = (i >> 3) & (HALF - 1);
        int b = i >> 16;
        int v = rnds[t];
        float4 val = feats4[(b * NPTS + v) * 8 + c];
        ((float4*)(out + OFF_VFEAT))[(b * HALF + t) * 8 + c] = val;
        return;
    }
    i -= WF;
    if (i < WP) {
        int t = i & (HALF - 1);
        int b = i >> 13;
        int v = rnds[t];
        int base = (b * NPTS + v) * 3;
        float x = pc[base + 0], y = pc[base + 1], z = pc[base + 2];
        int ob = OFF_VPC + (b * HALF + t) * 3;
        out[ob + 0] = x; out[ob + 1] = y; out[ob + 2] = z;
        g_valid[b][t] = make_float4(2.0f * x, 2.0f * y, 2.0f * z, sq3(x, y, z));
        int cid = cell_of(x, y, z);
        g_pcell[b][t] = cid;
        atomicAdd(&g_cnt[0][b][cid], 1);
        return;
    }
    i -= WP;
    if (i < WP) {
        int t = i & (HALF - 1);
        int b = i >> 13;
        int v = rnds[HALF + t];
        int base = (b * NPTS + v) * 3;
        float x = pc[base + 0], y = pc[base + 1], z = pc[base + 2];
        g_query[b][t] = make_float4(x, y, z, sq3(x, y, z));
        int cid = cell_of(x, y, z);
        g_qcell[b][t] = cid;
        atomicAdd(&g_cnt[1][b][cid], 1);
        return;
    }
    i -= WP;
    if (i < NPTS) out[OFF_RNDS + i] = (float)rnds[i];
}

// ---------------------------------------------------------------------------
// K2: exclusive scan of 4096 cells per (kind, batch)
// ---------------------------------------------------------------------------
__global__ void __launch_bounds__(1024) scan_kernel() {
    int kind = blockIdx.x >> 2;
    int b = blockIdx.x & 3;
    const int CPT = NC / 1024;  // 4 cells per thread
    int tid = threadIdx.x;

    int loc[CPT];
    int s = 0;
    const int* cnt = g_cnt[kind][b];
#pragma unroll
    for (int j = 0; j < CPT; ++j) { loc[j] = s; s += cnt[tid * CPT + j]; }

    __shared__ int sh[1024];
    sh[tid] = s;
    __syncthreads();
    for (int off = 1; off < 1024; off <<= 1) {
        int v = (tid >= off) ? sh[tid - off] : 0;
        __syncthreads();
        sh[tid] += v;
        __syncthreads();
    }
    int base = (tid > 0) ? sh[tid - 1] : 0;

    int* off_arr = g_off[kind][b];
    int* cur_arr = g_cur[kind][b];
#pragma unroll
    for (int j = 0; j < CPT; ++j) {
        int v = base + loc[j];
        off_arr[tid * CPT + j] = v;
        cur_arr[tid * CPT + j] = v;
    }
    if (tid == 1023) off_arr[NC] = sh[1023];
}

// ---------------------------------------------------------------------------
// K3: scatter into cell-sorted order (also store sorted-query cell id)
// ---------------------------------------------------------------------------
__global__ void scatter_kernel() {
    int i = blockIdx.x * blockDim.x + threadIdx.x;
    if (i >= 2 * BATCH * HALF) return;
    int kind = i >> 15;
    int b = (i >> 13) & (BATCH - 1);
    int t = i & (HALF - 1);
    if (kind == 0) {
        int cid = g_pcell[b][t];
        int pos = atomicAdd(&g_cur[0][b][cid], 1);
        g_spt[b][pos] = g_valid[b][t];
        g_sid[b][pos] = t;
    } else {
        int cid = g_qcell[b][t];
        int pos = atomicAdd(&g_cur[1][b][cid], 1);
        g_sq[b][pos] = g_query[b][t];
        g_sqid[b][pos] = t;
        g_sqc[b][pos] = cid;
    }
}

// ---------------------------------------------------------------------------
// K4: warp-per-query grid KNN.
// Phase 1: lanes 0..26 each own one cell of the 3x3x3 box (no prune — extra
// candidates are harmless). Warp-reduce top-2 (dedup-safe), warp-uniform
// termination bound. Rare continuation: shells r>=2 strided over lanes with
// per-cell box prune. Every scored candidate uses the exact reference-rounded
// formula; tie-break by original index => bit-identical to reference.
// ---------------------------------------------------------------------------
__global__ void __launch_bounds__(256) knn_kernel(float* __restrict__ out) {
    __shared__ float sbnd[GD + 1];
    if (threadIdx.x < GD + 1) sbnd[threadIdx.x] = c_bnd[threadIdx.x];
    __syncthreads();

    int w = (blockIdx.x * blockDim.x + threadIdx.x) >> 5;  // global warp id
    int lane = threadIdx.x & 31;
    int b = w >> 13;
    int s = w & (HALF - 1);

    float4 q = g_sq[b][s];          // broadcast load (same addr across warp)
    int qi = g_sqid[b][s];
    int qc = g_sqc[b][s];
    const float qx = q.x, qy = q.y, qz = q.z, q2 = q.w;

    int qcx = qc & (GD - 1);
    int qcy = (qc >> 4) & (GD - 1);
    int qcz = qc >> 8;

    const float INF = __int_as_float(0x7f800000);
    const float MARG = 1e-5f;
    float bd1 = INF, bd2 = INF;     // per-lane local top-2
    int bi1 = 0x7fffffff, bi2 = 0x7fffffff;

    const float4* __restrict__ pts = g_spt[b];
    const int* __restrict__ ids = g_sid[b];
    const int* __restrict__ offs = g_off[0][b];

    // ---- Phase 1: 3x3x3 box, one cell per lane, unconditional scoring ----
    if (lane < 27) {
        int dx = lane % 3 - 1;
        int dy = (lane / 3) % 3 - 1;
        int dz = lane / 9 - 1;
        int cx = qcx + dx, cy = qcy + dy, cz = qcz + dz;
        if (cx >= 0 && cx < GD && cy >= 0 && cy < GD && cz >= 0 && cz < GD) {
            int cid = (cz * GD + cy) * GD + cx;
            int p0 = __ldg(&offs[cid]), p1 = __ldg(&offs[cid + 1]);
            for (int p = p0; p < p1; ++p) {
                float4 P = pts[p];
                float dot2 = __fadd_rn(__fadd_rn(__fmul_rn(qx, P.x),
                                                 __fmul_rn(qy, P.y)),
                                       __fmul_rn(qz, P.z));
                float d2 = __fsub_rn(__fadd_rn(q2, P.w), dot2);
                ins2(d2, ids[p], bd1, bi1, bd2, bi2);
            }
        }
    }

    warp_reduce_top2(bd1, bi1, bd2, bi2);

    // ---- Termination + rare outer shells ----
    for (int r = 1; r < GD; ++r) {
        // lower bound on distance to any unvisited cell (outside box qc +- r)
        if (bd2 < INF) {
            float lb = INF;
            if (qcx - r > 0)      lb = fminf(lb, qx - sbnd[qcx - r]);
            if (qcx + r < GD - 1) lb = fminf(lb, sbnd[qcx + r + 1] - qx);
            if (qcy - r > 0)      lb = fminf(lb, qy - sbnd[qcy - r]);
            if (qcy + r < GD - 1) lb = fminf(lb, sbnd[qcy + r + 1] - qy);
            if (qcz - r > 0)      lb = fminf(lb, qz - sbnd[qcz - r]);
            if (qcz + r < GD - 1) lb = fminf(lb, sbnd[qcz + r + 1] - qz);
            float lba = fmaxf(lb - MARG, 0.0f);
            if (lba * lba > bd2 * 1.001f + 1e-4f) break;
        }

        // score shell at radius r+1 (box side 2r+3), lanes strided over box
        int rr = r + 1;
        int side = 2 * rr + 1;
        int ncell = side * side * side;
        for (int ci = lane; ci < ncell; ci += 32) {
            int dx = ci % side - rr;
            int dy = (ci / side) % side - rr;
            int dz = ci / (side * side) - rr;
            if (abs(dx) < rr && abs(dy) < rr && abs(dz) < rr) continue;  // interior
            int cx = qcx + dx, cy = qcy + dy, cz = qcz + dz;
            if (cx < 0 || cx >= GD || cy < 0 || cy >= GD || cz < 0 || cz >= GD) continue;
            // conservative box prune
            float lx = sbnd[cx] - MARG, hx = sbnd[cx + 1] + MARG;
            float ly = sbnd[cy] - MARG, hy = sbnd[cy + 1] + MARG;
            float lz = sbnd[cz] - MARG, hz = sbnd[cz + 1] + MARG;
            float ddx = (qx < lx) ? (lx - qx) : ((qx > hx) ? (qx - hx) : 0.0f);
            float ddy = (qy < ly) ? (ly - qy) : ((qy > hy) ? (qy - hy) : 0.0f);
            float ddz = (qz < lz) ? (lz - qz) : ((qz > hz) ? (qz - hz) : 0.0f);
            float d2b = ddx * ddx + ddy * ddy + ddz * ddz;
            if (bd2 < INF && d2b > bd2 * 1.001f + 1e-4f) continue;

            int cid = (cz * GD + cy) * GD + cx;
            int p0 = __ldg(&offs[cid]), p1 = __ldg(&offs[cid + 1]);
            for (int p = p0; p < p1; ++p) {
                float4 P = pts[p];
                float dot2 = __fadd_rn(__fadd_rn(__fmul_rn(qx, P.x),
                                                 __fmul_rn(qy, P.y)),
                                       __fmul_rn(qz, P.z));
                float d2 = __fsub_rn(__fadd_rn(q2, P.w), dot2);
                ins2(d2, ids[p], bd1, bi1, bd2, bi2);
            }
        }

        warp_reduce_top2(bd1, bi1, bd2, bi2);
    }

    if (lane == 0) out[OFF_NIDX + (b << 13) + qi] = (float)bi2;
}

// ---------------------------------------------------------------------------
extern "C" void kernel_launch(void* const* d_in, const int* in_sizes, int n_in,
                              void* d_out, int out_size) {
    const float*  pc    = (const float*)d_in[0];
    const float4* feats = (const float4*)d_in[1];
    const int*    rnds  = (const int*)d_in[2];
    float*        out   = (float*)d_out;
    (void)in_sizes; (void)n_in; (void)out_size;

    init_kernel<<<(2 * BATCH * NC + 255) / 256, 256>>>();

    const int total = BATCH * HALF * 8 + 2 * BATCH * HALF + NPTS;  // 344064
    gather_kernel<<<total / 256, 256>>>(pc, feats, rnds, out);

    scan_kernel<<<2 * BATCH, 1024>>>();
    scatter_kernel<<<(2 * BATCH * HALF + 255) / 256, 256>>>();

    // one warp per query: 32768 warps = 4096 blocks of 256 threads
    knn_kernel<<<BATCH * HALF * 32 / 256, 256>>>(out);
}

// round 7
// speedup vs baseline: 4.2397x; 2.3274x over previous
#include <cuda_runtime.h>

// Problem constants
#define BATCH   4
#define NPTS    16384
#define HALF    8192
#define FDIM    32
#define GD      16               // cells per axis (in CDF/u-space)
#define NC      (GD*GD*GD)       // 4096 cells per batch

// Output layout (concatenated tuple, float32)
#define OFF_VPC   0
#define OFF_VFEAT (BATCH * HALF * 3)                  // 98304
#define OFF_NIDX  (OFF_VFEAT + BATCH * HALF * FDIM)   // 1146880
#define OFF_RNDS  (OFF_NIDX + BATCH * HALF)           // 1179648

// Cell boundaries in x-space: standard normal quantiles Phi^-1(i/16).
__constant__ float c_bnd[GD + 1] = {
    -1e30f,
    -1.5341206f, -1.1503494f, -0.8871466f, -0.6744898f,
    -0.4887764f, -0.3186394f, -0.1573107f,  0.0f,
     0.1573107f,  0.3186394f,  0.4887764f,  0.6744898f,
     0.8871466f,  1.1503494f,  1.5341206f,
     1e30f
};

// ---------------------------------------------------------------------------
// Scratch (device globals; no allocation allowed)
// ---------------------------------------------------------------------------
__device__ float4 g_valid[BATCH][HALF];   // (2x, 2y, 2z, p2) original order
__device__ float4 g_query[BATCH][HALF];   // (x, y, z, q2)  original order
__device__ int    g_pcell[BATCH][HALF];   // point cell id
__device__ int    g_qcell[BATCH][HALF];   // query cell id
__device__ int    g_cnt[2][BATCH][NC];    // histograms: 0 = points, 1 = queries
__device__ int    g_off[2][BATCH][NC+1];  // exclusive offsets
__device__ int    g_cur[2][BATCH][NC];    // scatter cursors
__device__ float4 g_spt[BATCH][HALF];     // cell-sorted points (2x,2y,2z,p2)
__device__ int    g_sid[BATCH][HALF];     // original point index
__device__ float4 g_sq[BATCH][HALF];      // cell-sorted queries (x,y,z,q2)
__device__ int    g_sqid[BATCH][HALF];    // original query index
__device__ int    g_sqc[BATCH][HALF];     // cell id of sorted query

// ||v||^2 left-to-right, no FMA contraction (match jax fp32 semantics)
__device__ __forceinline__ float sq3(float x, float y, float z) {
    return __fadd_rn(__fadd_rn(__fmul_rn(x, x), __fmul_rn(y, y)), __fmul_rn(z, z));
}

// CDF-space axis cell: u = Phi(x) = 0.5*(1+erf(x/sqrt(2))), cell = floor(u*GD)
__device__ __forceinline__ int axis_cell(float x) {
    float u = __fmaf_rn(erff(x * 0.70710678f), 0.5f, 0.5f);
    int c = (int)(u * (float)GD);
    return max(0, min(GD - 1, c));
}
__device__ __forceinline__ int cell_of(float x, float y, float z) {
    return (axis_cell(z) * GD + axis_cell(y)) * GD + axis_cell(x);
}

// strict-order comparator matching stable top_k: smaller dist, then smaller idx
__device__ __forceinline__ bool lt2(float d, int i, float e, int j) {
    return d < e || (d == e && i < j);
}

// Insert candidate (d, i) into sorted top-2 state, deduping by id.
__device__ __forceinline__ void ins2(float d, int i,
                                     float& bd1, int& bi1,
                                     float& bd2, int& bi2) {
    if (i == bi1 || i == bi2) return;
    if (lt2(d, i, bd1, bi1)) {
        bd2 = bd1; bi2 = bi1; bd1 = d; bi1 = i;
    } else if (lt2(d, i, bd2, bi2)) {
        bd2 = d; bi2 = i;
    }
}

// Warp butterfly top-2 reduction using dedup-safe insertion merge.
__device__ __forceinline__ void warp_reduce_top2(float& bd1, int& bi1,
                                                 float& bd2, int& bi2) {
#pragma unroll
    for (int o = 16; o > 0; o >>= 1) {
        float e1 = __shfl_xor_sync(0xFFFFFFFFu, bd1, o);
        float e2 = __shfl_xor_sync(0xFFFFFFFFu, bd2, o);
        int j1 = __shfl_xor_sync(0xFFFFFFFFu, bi1, o);
        int j2 = __shfl_xor_sync(0xFFFFFFFFu, bi2, o);
        ins2(e1, j1, bd1, bi1, bd2, bi2);
        ins2(e2, j2, bd1, bi1, bd2, bi2);
    }
}

// exact reference-rounded candidate scoring
__device__ __forceinline__ float score(float qx, float qy, float qz, float q2,
                                       float4 P) {
    float dot2 = __fadd_rn(__fadd_rn(__fmul_rn(qx, P.x), __fmul_rn(qy, P.y)),
                           __fmul_rn(qz, P.z));
    return __fsub_rn(__fadd_rn(q2, P.w), dot2);
}

// ---------------------------------------------------------------------------
// K0: zero histograms (graph replays => must reset every launch)
// ---------------------------------------------------------------------------
__global__ void init_kernel() {
    int i = blockIdx.x * blockDim.x + threadIdx.x;
    if (i < 2 * BATCH * NC) ((int*)g_cnt)[i] = 0;
}

// ---------------------------------------------------------------------------
// K1: gathers + binning + histogram
// ---------------------------------------------------------------------------
__global__ void gather_kernel(const float* __restrict__ pc,
                              const float4* __restrict__ feats4,
                              const int* __restrict__ rnds,
                              float* __restrict__ out) {
    int i = blockIdx.x * blockDim.x + threadIdx.x;
    const int WF = BATCH * HALF * 8;
    const int WP = BATCH * HALF;

    if (i < WF) {
        int c = i & 7;
        int t = (i >> 3) & (HALF - 1);
        int b = i >> 16;
        int v = rnds[t];
        float4 val = feats4[(b * NPTS + v) * 8 + c];
        ((float4*)(out + OFF_VFEAT))[(b * HALF + t) * 8 + c] = val;
        return;
    }
    i -= WF;
    if (i < WP) {
        int t = i & (HALF - 1);
        int b = i >> 13;
        int v = rnds[t];
        int base = (b * NPTS + v) * 3;
        float x = pc[base + 0], y = pc[base + 1], z = pc[base + 2];
        int ob = OFF_VPC + (b * HALF + t) * 3;
        out[ob + 0] = x; out[ob + 1] = y; out[ob + 2] = z;
        g_valid[b][t] = make_float4(2.0f * x, 2.0f * y, 2.0f * z, sq3(x, y, z));
        int cid = cell_of(x, y, z);
        g_pcell[b][t] = cid;
        atomicAdd(&g_cnt[0][b][cid], 1);
        return;
    }
    i -= WP;
    if (i < WP) {
        int t = i & (HALF - 1);
        int b = i >> 13;
        int v = rnds[HALF + t];
        int base = (b * NPTS + v) * 3;
        float x = pc[base + 0], y = pc[base + 1], z = pc[base + 2];
        g_query[b][t] = make_float4(x, y, z, sq3(x, y, z));
        int cid = cell_of(x, y, z);
        g_qcell[b][t] = cid;
        atomicAdd(&g_cnt[1][b][cid], 1);
        return;
    }
    i -= WP;
    if (i < NPTS) out[OFF_RNDS + i] = (float)rnds[i];
}

// ---------------------------------------------------------------------------
// K2: exclusive scan of 4096 cells per (kind, batch)
// ---------------------------------------------------------------------------
__global__ void __launch_bounds__(1024) scan_kernel() {
    int kind = blockIdx.x >> 2;
    int b = blockIdx.x & 3;
    const int CPT = NC / 1024;  // 4 cells per thread
    int tid = threadIdx.x;

    int loc[CPT];
    int s = 0;
    const int* cnt = g_cnt[kind][b];
#pragma unroll
    for (int j = 0; j < CPT; ++j) { loc[j] = s; s += cnt[tid * CPT + j]; }

    __shared__ int sh[1024];
    sh[tid] = s;
    __syncthreads();
    for (int off = 1; off < 1024; off <<= 1) {
        int v = (tid >= off) ? sh[tid - off] : 0;
        __syncthreads();
        sh[tid] += v;
        __syncthreads();
    }
    int base = (tid > 0) ? sh[tid - 1] : 0;

    int* off_arr = g_off[kind][b];
    int* cur_arr = g_cur[kind][b];
#pragma unroll
    for (int j = 0; j < CPT; ++j) {
        int v = base + loc[j];
        off_arr[tid * CPT + j] = v;
        cur_arr[tid * CPT + j] = v;
    }
    if (tid == 1023) off_arr[NC] = sh[1023];
}

// ---------------------------------------------------------------------------
// K3: scatter into cell-sorted order (also store sorted-query cell id)
// ---------------------------------------------------------------------------
__global__ void scatter_kernel() {
    int i = blockIdx.x * blockDim.x + threadIdx.x;
    if (i >= 2 * BATCH * HALF) return;
    int kind = i >> 15;
    int b = (i >> 13) & (BATCH - 1);
    int t = i & (HALF - 1);
    if (kind == 0) {
        int cid = g_pcell[b][t];
        int pos = atomicAdd(&g_cur[0][b][cid], 1);
        g_spt[b][pos] = g_valid[b][t];
        g_sid[b][pos] = t;
    } else {
        int cid = g_qcell[b][t];
        int pos = atomicAdd(&g_cur[1][b][cid], 1);
        g_sq[b][pos] = g_query[b][t];
        g_sqid[b][pos] = t;
        g_sqc[b][pos] = cid;
    }
}

// ---------------------------------------------------------------------------
// K4: warp-per-query KNN, bounded worst case.
//  P1: 3x3x3 box (lane-owned cells), reduce, r=1 termination check.
//  P2: 5x5x5 ring (lane-strided, box prune), reduce, r=2 check.
//  P3: fallback = warp-parallel brute force over ALL points (superset-safe,
//      coalesced, ~256 pts/lane) — eliminates tail stragglers by construction.
// Every scored candidate uses the exact reference-rounded formula; id-dedup
// top-2 merge => order-independent, bit-identical to reference.
// ---------------------------------------------------------------------------
// warp-uniform: can any unvisited cell (outside box qc +- r) beat bd2?
__device__ __forceinline__ bool term_ok(int qcx, int qcy, int qcz, int r,
                                        float qx, float qy, float qz,
                                        float bd2, const float* sbnd) {
    const float INF = __int_as_float(0x7f800000);
    if (!(bd2 < INF)) return false;
    float lb = INF;
    if (qcx - r > 0)      lb = fminf(lb, qx - sbnd[qcx - r]);
    if (qcx + r < GD - 1) lb = fminf(lb, sbnd[qcx + r + 1] - qx);
    if (qcy - r > 0)      lb = fminf(lb, qy - sbnd[qcy - r]);
    if (qcy + r < GD - 1) lb = fminf(lb, sbnd[qcy + r + 1] - qy);
    if (qcz - r > 0)      lb = fminf(lb, qz - sbnd[qcz - r]);
    if (qcz + r < GD - 1) lb = fminf(lb, sbnd[qcz + r + 1] - qz);
    float lba = fmaxf(lb - 1e-5f, 0.0f);
    return lba * lba > bd2 * 1.001f + 1e-4f;
}

__global__ void __launch_bounds__(256) knn_kernel(float* __restrict__ out) {
    __shared__ float sbnd[GD + 1];
    if (threadIdx.x < GD + 1) sbnd[threadIdx.x] = c_bnd[threadIdx.x];
    __syncthreads();

    int w = (blockIdx.x * blockDim.x + threadIdx.x) >> 5;  // global warp id
    int lane = threadIdx.x & 31;
    int b = w >> 13;
    int s = w & (HALF - 1);

    float4 q = g_sq[b][s];          // broadcast load
    int qi = g_sqid[b][s];
    int qc = g_sqc[b][s];
    const float qx = q.x, qy = q.y, qz = q.z, q2 = q.w;

    int qcx = qc & (GD - 1);
    int qcy = (qc >> 4) & (GD - 1);
    int qcz = qc >> 8;

    const float INF = __int_as_float(0x7f800000);
    const float MARG = 1e-5f;
    float bd1 = INF, bd2 = INF;
    int bi1 = 0x7fffffff, bi2 = 0x7fffffff;

    const float4* __restrict__ pts = g_spt[b];
    const int* __restrict__ ids = g_sid[b];
    const int* __restrict__ offs = g_off[0][b];

    // ---- Phase 1: 3x3x3 box, one cell per lane ----
    if (lane < 27) {
        int dx = lane % 3 - 1;
        int dy = (lane / 3) % 3 - 1;
        int dz = lane / 9 - 1;
        int cx = qcx + dx, cy = qcy + dy, cz = qcz + dz;
        if (cx >= 0 && cx < GD && cy >= 0 && cy < GD && cz >= 0 && cz < GD) {
            int cid = (cz * GD + cy) * GD + cx;
            int p0 = __ldg(&offs[cid]), p1 = __ldg(&offs[cid + 1]);
            for (int p = p0; p < p1; ++p)
                ins2(score(qx, qy, qz, q2, pts[p]), ids[p], bd1, bi1, bd2, bi2);
        }
    }
    warp_reduce_top2(bd1, bi1, bd2, bi2);

    if (!term_ok(qcx, qcy, qcz, 1, qx, qy, qz, bd2, sbnd)) {
        // ---- Phase 2: 5x5x5 ring (125 cells incl. interior skip) ----
#pragma unroll
        for (int base = 0; base < 125; base += 32) {
            int ci = base + lane;
            if (ci < 125) {
                int dx = ci % 5 - 2;
                int dy = (ci / 5) % 5 - 2;
                int dz = ci / 25 - 2;
                bool interior = (dx >= -1 && dx <= 1 && dy >= -1 && dy <= 1 &&
                                 dz >= -1 && dz <= 1);
                int cx = qcx + dx, cy = qcy + dy, cz = qcz + dz;
                if (!interior && cx >= 0 && cx < GD && cy >= 0 && cy < GD &&
                    cz >= 0 && cz < GD) {
                    // conservative box prune
                    float lx = sbnd[cx] - MARG, hx = sbnd[cx + 1] + MARG;
                    float ly = sbnd[cy] - MARG, hy = sbnd[cy + 1] + MARG;
                    float lz = sbnd[cz] - MARG, hz = sbnd[cz + 1] + MARG;
                    float ddx = (qx < lx) ? (lx - qx) : ((qx > hx) ? (qx - hx) : 0.0f);
                    float ddy = (qy < ly) ? (ly - qy) : ((qy > hy) ? (qy - hy) : 0.0f);
                    float ddz = (qz < lz) ? (lz - qz) : ((qz > hz) ? (qz - hz) : 0.0f);
                    float d2b = ddx * ddx + ddy * ddy + ddz * ddz;
                    if (!(bd2 < INF) || d2b <= bd2 * 1.001f + 1e-4f) {
                        int cid = (cz * GD + cy) * GD + cx;
                        int p0 = __ldg(&offs[cid]), p1 = __ldg(&offs[cid + 1]);
                        for (int p = p0; p < p1; ++p)
                            ins2(score(qx, qy, qz, q2, pts[p]), ids[p],
                                 bd1, bi1, bd2, bi2);
                    }
                }
            }
        }
        warp_reduce_top2(bd1, bi1, bd2, bi2);

        if (!term_ok(qcx, qcy, qcz, 2, qx, qy, qz, bd2, sbnd)) {
            // ---- Phase 3: bounded fallback — full warp-parallel brute force.
            // Superset of everything; coalesced float4 streams; ~256 pts/lane.
            for (int p = lane; p < HALF; p += 32)
                ins2(score(qx, qy, qz, q2, pts[p]), ids[p], bd1, bi1, bd2, bi2);
            warp_reduce_top2(bd1, bi1, bd2, bi2);
        }
    }

    if (lane == 0) out[OFF_NIDX + (b << 13) + qi] = (float)bi2;
}

// ---------------------------------------------------------------------------
extern "C" void kernel_launch(void* const* d_in, const int* in_sizes, int n_in,
                              void* d_out, int out_size) {
    const float*  pc    = (const float*)d_in[0];
    const float4* feats = (const float4*)d_in[1];
    const int*    rnds  = (const int*)d_in[2];
    float*        out   = (float*)d_out;
    (void)in_sizes; (void)n_in; (void)out_size;

    init_kernel<<<(2 * BATCH * NC + 255) / 256, 256>>>();

    const int total = BATCH * HALF * 8 + 2 * BATCH * HALF + NPTS;  // 344064
    gather_kernel<<<total / 256, 256>>>(pc, feats, rnds, out);

    scan_kernel<<<2 * BATCH, 1024>>>();
    scatter_kernel<<<(2 * BATCH * HALF + 255) / 256, 256>>>();

    // one warp per query: 32768 warps = 4096 blocks of 256 threads
    knn_kernel<<<BATCH * HALF * 32 / 256, 256>>>(out);
}

// round 8
// speedup vs baseline: 4.9349x; 1.1640x over previous
#include <cuda_runtime.h>

// Problem constants
#define BATCH   4
#define NPTS    16384
#define HALF    8192
#define FDIM    32
#define GD      16               // cells per axis (in CDF/u-space)
#define NC      (GD*GD*GD)       // 4096 cells per batch

// Output layout (concatenated tuple, float32)
#define OFF_VPC   0
#define OFF_VFEAT (BATCH * HALF * 3)                  // 98304
#define OFF_NIDX  (OFF_VFEAT + BATCH * HALF * FDIM)   // 1146880
#define OFF_RNDS  (OFF_NIDX + BATCH * HALF)           // 1179648

// Cell boundaries in x-space: standard normal quantiles Phi^-1(i/16).
__constant__ float c_bnd[GD + 1] = {
    -1e30f,
    -1.5341206f, -1.1503494f, -0.8871466f, -0.6744898f,
    -0.4887764f, -0.3186394f, -0.1573107f,  0.0f,
     0.1573107f,  0.3186394f,  0.4887764f,  0.6744898f,
     0.8871466f,  1.1503494f,  1.5341206f,
     1e30f
};

// ---------------------------------------------------------------------------
// Scratch (device globals; no allocation allowed)
// ---------------------------------------------------------------------------
__device__ float4 g_valid[BATCH][HALF];
__device__ float4 g_query[BATCH][HALF];
__device__ int    g_pcell[BATCH][HALF];
__device__ int    g_qcell[BATCH][HALF];
__device__ int    g_cnt[2][BATCH][NC];
__device__ int    g_off[2][BATCH][NC+1];
__device__ int    g_cur[2][BATCH][NC];
__device__ float4 g_spt[BATCH][HALF];     // cell-sorted points (2x,2y,2z,p2)
__device__ int    g_sid[BATCH][HALF];     // original point index
__device__ float4 g_sq[BATCH][HALF];      // cell-sorted queries (x,y,z,q2)
__device__ int    g_sqid[BATCH][HALF];
__device__ int    g_sqc[BATCH][HALF];

// ||v||^2 left-to-right, no FMA contraction (match jax fp32 semantics)
__device__ __forceinline__ float sq3(float x, float y, float z) {
    return __fadd_rn(__fadd_rn(__fmul_rn(x, x), __fmul_rn(y, y)), __fmul_rn(z, z));
}

__device__ __forceinline__ int axis_cell(float x) {
    float u = __fmaf_rn(erff(x * 0.70710678f), 0.5f, 0.5f);
    int c = (int)(u * (float)GD);
    return max(0, min(GD - 1, c));
}
__device__ __forceinline__ int cell_of(float x, float y, float z) {
    return (axis_cell(z) * GD + axis_cell(y)) * GD + axis_cell(x);
}

__device__ __forceinline__ bool lt2(float d, int i, float e, int j) {
    return d < e || (d == e && i < j);
}

// Insert candidate (d, i) into sorted top-2 state, deduping by id.
__device__ __forceinline__ void ins2(float d, int i,
                                     float& bd1, int& bi1,
                                     float& bd2, int& bi2) {
    if (i == bi1 || i == bi2) return;
    if (lt2(d, i, bd1, bi1)) {
        bd2 = bd1; bi2 = bi1; bd1 = d; bi1 = i;
    } else if (lt2(d, i, bd2, bi2)) {
        bd2 = d; bi2 = i;
    }
}

__device__ __forceinline__ void warp_reduce_top2(float& bd1, int& bi1,
                                                 float& bd2, int& bi2) {
#pragma unroll
    for (int o = 16; o > 0; o >>= 1) {
        float e1 = __shfl_xor_sync(0xFFFFFFFFu, bd1, o);
        float e2 = __shfl_xor_sync(0xFFFFFFFFu, bd2, o);
        int j1 = __shfl_xor_sync(0xFFFFFFFFu, bi1, o);
        int j2 = __shfl_xor_sync(0xFFFFFFFFu, bi2, o);
        ins2(e1, j1, bd1, bi1, bd2, bi2);
        ins2(e2, j2, bd1, bi1, bd2, bi2);
    }
}

__device__ __forceinline__ float score(float qx, float qy, float qz, float q2,
                                       float4 P) {
    float dot2 = __fadd_rn(__fadd_rn(__fmul_rn(qx, P.x), __fmul_rn(qy, P.y)),
                           __fmul_rn(qz, P.z));
    return __fsub_rn(__fadd_rn(q2, P.w), dot2);
}

// ---------------------------------------------------------------------------
// K0: zero histograms
// ---------------------------------------------------------------------------
__global__ void init_kernel() {
    int i = blockIdx.x * blockDim.x + threadIdx.x;
    if (i < 2 * BATCH * NC) ((int*)g_cnt)[i] = 0;
}

// ---------------------------------------------------------------------------
// K1: gathers + binning + histogram
// ---------------------------------------------------------------------------
__global__ void gather_kernel(const float* __restrict__ pc,
                              const float4* __restrict__ feats4,
                              const int* __restrict__ rnds,
                              float* __restrict__ out) {
    int i = blockIdx.x * blockDim.x + threadIdx.x;
    const int WF = BATCH * HALF * 8;
    const int WP = BATCH * HALF;

    if (i < WF) {
        int c = i & 7;
        int t = (i >> 3) & (HALF - 1);
        int b = i >> 16;
        int v = rnds[t];
        float4 val = feats4[(b * NPTS + v) * 8 + c];
        ((float4*)(out + OFF_VFEAT))[(b * HALF + t) * 8 + c] = val;
        return;
    }
    i -= WF;
    if (i < WP) {
        int t = i & (HALF - 1);
        int b = i >> 13;
        int v = rnds[t];
        int base = (b * NPTS + v) * 3;
        float x = pc[base + 0], y = pc[base + 1], z = pc[base + 2];
        int ob = OFF_VPC + (b * HALF + t) * 3;
        out[ob + 0] = x; out[ob + 1] = y; out[ob + 2] = z;
        g_valid[b][t] = make_float4(2.0f * x, 2.0f * y, 2.0f * z, sq3(x, y, z));
        int cid = cell_of(x, y, z);
        g_pcell[b][t] = cid;
        atomicAdd(&g_cnt[0][b][cid], 1);
        return;
    }
    i -= WP;
    if (i < WP) {
        int t = i & (HALF - 1);
        int b = i >> 13;
        int v = rnds[HALF + t];
        int base = (b * NPTS + v) * 3;
        float x = pc[base + 0], y = pc[base + 1], z = pc[base + 2];
        g_query[b][t] = make_float4(x, y, z, sq3(x, y, z));
        int cid = cell_of(x, y, z);
        g_qcell[b][t] = cid;
        atomicAdd(&g_cnt[1][b][cid], 1);
        return;
    }
    i -= WP;
    if (i < NPTS) out[OFF_RNDS + i] = (float)rnds[i];
}

// ---------------------------------------------------------------------------
// K2: exclusive scan via two-level warp shuffle scan (2 syncthreads)
// ---------------------------------------------------------------------------
__global__ void __launch_bounds__(1024) scan_kernel() {
    int kind = blockIdx.x >> 2;
    int b = blockIdx.x & 3;
    const int CPT = NC / 1024;  // 4
    int tid = threadIdx.x;
    int lane = tid & 31;
    int wid = tid >> 5;

    int loc[CPT];
    int s = 0;
    const int* cnt = g_cnt[kind][b];
#pragma unroll
    for (int j = 0; j < CPT; ++j) { loc[j] = s; s += cnt[tid * CPT + j]; }

    // warp inclusive scan of s
    int inc = s;
#pragma unroll
    for (int o = 1; o < 32; o <<= 1) {
        int v = __shfl_up_sync(0xFFFFFFFFu, inc, o);
        if (lane >= o) inc += v;
    }
    __shared__ int wsum[32];
    if (lane == 31) wsum[wid] = inc;
    __syncthreads();
    if (wid == 0) {
        int v = wsum[lane];
        int wi = v;
#pragma unroll
        for (int o = 1; o < 32; o <<= 1) {
            int u = __shfl_up_sync(0xFFFFFFFFu, wi, o);
            if (lane >= o) wi += u;
        }
        wsum[lane] = wi - v;   // exclusive warp offsets
    }
    __syncthreads();
    int base = wsum[wid] + (inc - s);   // exclusive prefix for this thread

    int* off_arr = g_off[kind][b];
    int* cur_arr = g_cur[kind][b];
#pragma unroll
    for (int j = 0; j < CPT; ++j) {
        int v = base + loc[j];
        off_arr[tid * CPT + j] = v;
        cur_arr[tid * CPT + j] = v;
    }
    if (tid == 1023) off_arr[NC] = base + s;
}

// ---------------------------------------------------------------------------
// K3: scatter into cell-sorted order
// ---------------------------------------------------------------------------
__global__ void scatter_kernel() {
    int i = blockIdx.x * blockDim.x + threadIdx.x;
    if (i >= 2 * BATCH * HALF) return;
    int kind = i >> 15;
    int b = (i >> 13) & (BATCH - 1);
    int t = i & (HALF - 1);
    if (kind == 0) {
        int cid = g_pcell[b][t];
        int pos = atomicAdd(&g_cur[0][b][cid], 1);
        g_spt[b][pos] = g_valid[b][t];
        g_sid[b][pos] = t;
    } else {
        int cid = g_qcell[b][t];
        int pos = atomicAdd(&g_cur[1][b][cid], 1);
        g_sq[b][pos] = g_query[b][t];
        g_sqid[b][pos] = t;
        g_sqc[b][pos] = cid;
    }
}

// ---------------------------------------------------------------------------
// K4: warp-per-query KNN with run-based cooperative box scan.
// Cells with consecutive cx are contiguous in cid => contiguous point ranges.
// A (2R+1)^3 box = (2R+1)^2 contiguous runs. Lanes fetch run extents,
// warp-scan lengths, then all lanes stride the concatenated candidates
// (coalesced float4 loads). ids[] loaded lazily (only when d2 <= bd2 —
// a candidate with d2 > bd2 can never insert regardless of id => exact).
// Dedup-by-id ins2 makes rescanning interior cells in the R=2 pass harmless.
// ---------------------------------------------------------------------------
template <int R>
__device__ __forceinline__ void scan_box(int qcx, int qcy, int qcz,
                                         float qx, float qy, float qz, float q2,
                                         const float4* __restrict__ pts,
                                         const int* __restrict__ ids,
                                         const int* __restrict__ offs,
                                         int lane,
                                         float& bd1, int& bi1,
                                         float& bd2, int& bi2) {
    const int NR = (2 * R + 1) * (2 * R + 1);
    int p0 = 0, len = 0;
    if (lane < NR) {
        int dy = lane % (2 * R + 1) - R;
        int dz = lane / (2 * R + 1) - R;
        int cy = qcy + dy, cz = qcz + dz;
        if (cy >= 0 && cy < GD && cz >= 0 && cz < GD) {
            int cx0 = max(qcx - R, 0), cx1 = min(qcx + R, GD - 1);
            int rowbase = (cz * GD + cy) * GD;
            p0 = __ldg(&offs[rowbase + cx0]);
            len = __ldg(&offs[rowbase + cx1 + 1]) - p0;
        }
    }
    // warp inclusive scan of len
    int inc = len;
#pragma unroll
    for (int o = 1; o < 32; o <<= 1) {
        int v = __shfl_up_sync(0xFFFFFFFFu, inc, o);
        if (lane >= o) inc += v;
    }
    int excl = inc - len;
    int T = __shfl_sync(0xFFFFFFFFu, inc, NR - 1);

    for (int base = 0; base < T; base += 32) {
        int c = base + lane;
        bool active = c < T;
        int cc = active ? c : (T - 1);
        // binary search: largest run k (k < NR) with excl_k <= cc
        int lo = 0;
#pragma unroll
        for (int step = 16; step > 0; step >>= 1) {
            int mid = lo + step;
            int v = __shfl_sync(0xFFFFFFFFu, excl, min(mid, 31));
            if (mid < NR && v <= cc) lo = mid;
        }
        int rp0 = __shfl_sync(0xFFFFFFFFu, p0, lo);
        int rex = __shfl_sync(0xFFFFFFFFu, excl, lo);
        int p = rp0 + (cc - rex);
        float4 P = pts[p];
        if (active) {
            float d2 = score(qx, qy, qz, q2, P);
            if (d2 <= bd2) {            // lazy id: only when insert is possible
                ins2(d2, ids[p], bd1, bi1, bd2, bi2);
            }
        }
    }
    warp_reduce_top2(bd1, bi1, bd2, bi2);
}

// warp-uniform: can any unvisited cell (outside box qc +- r) beat bd2?
__device__ __forceinline__ bool term_ok(int qcx, int qcy, int qcz, int r,
                                        float qx, float qy, float qz,
                                        float bd2, const float* sbnd) {
    const float INF = __int_as_float(0x7f800000);
    if (!(bd2 < INF)) return false;
    float lb = INF;
    if (qcx - r > 0)      lb = fminf(lb, qx - sbnd[qcx - r]);
    if (qcx + r < GD - 1) lb = fminf(lb, sbnd[qcx + r + 1] - qx);
    if (qcy - r > 0)      lb = fminf(lb, qy - sbnd[qcy - r]);
    if (qcy + r < GD - 1) lb = fminf(lb, sbnd[qcy + r + 1] - qy);
    if (qcz - r > 0)      lb = fminf(lb, qz - sbnd[qcz - r]);
    if (qcz + r < GD - 1) lb = fminf(lb, sbnd[qcz + r + 1] - qz);
    float lba = fmaxf(lb - 1e-5f, 0.0f);
    return lba * lba > bd2 * 1.001f + 1e-4f;
}

__global__ void __launch_bounds__(256) knn_kernel(float* __restrict__ out) {
    __shared__ float sbnd[GD + 1];
    if (threadIdx.x < GD + 1) sbnd[threadIdx.x] = c_bnd[threadIdx.x];
    __syncthreads();

    int w = (blockIdx.x * blockDim.x + threadIdx.x) >> 5;
    int lane = threadIdx.x & 31;
    int b = w >> 13;
    int s = w & (HALF - 1);

    float4 q = g_sq[b][s];
    int qi = g_sqid[b][s];
    int qc = g_sqc[b][s];
    const float qx = q.x, qy = q.y, qz = q.z, q2 = q.w;

    int qcx = qc & (GD - 1);
    int qcy = (qc >> 4) & (GD - 1);
    int qcz = qc >> 8;

    const float INF = __int_as_float(0x7f800000);
    float bd1 = INF, bd2 = INF;
    int bi1 = 0x7fffffff, bi2 = 0x7fffffff;

    const float4* __restrict__ pts = g_spt[b];
    const int* __restrict__ ids = g_sid[b];
    const int* __restrict__ offs = g_off[0][b];

    // Phase 1: 3x3x3 box as 9 contiguous runs
    scan_box<1>(qcx, qcy, qcz, qx, qy, qz, q2, pts, ids, offs, lane,
                bd1, bi1, bd2, bi2);

    if (!term_ok(qcx, qcy, qcz, 1, qx, qy, qz, bd2, sbnd)) {
        // Phase 2: 5x5x5 box as 25 runs (interior rescan deduped by id)
        scan_box<2>(qcx, qcy, qcz, qx, qy, qz, q2, pts, ids, offs, lane,
                    bd1, bi1, bd2, bi2);

        if (!term_ok(qcx, qcy, qcz, 2, qx, qy, qz, bd2, sbnd)) {
            // Phase 3: bounded fallback — full warp-parallel brute force
            for (int p = lane; p < HALF; p += 32) {
                float d2 = score(qx, qy, qz, q2, pts[p]);
                if (d2 <= bd2) ins2(d2, ids[p], bd1, bi1, bd2, bi2);
            }
            warp_reduce_top2(bd1, bi1, bd2, bi2);
        }
    }

    if (lane == 0) out[OFF_NIDX + (b << 13) + qi] = (float)bi2;
}

// ---------------------------------------------------------------------------
extern "C" void kernel_launch(void* const* d_in, const int* in_sizes, int n_in,
                              void* d_out, int out_size) {
    const float*  pc    = (const float*)d_in[0];
    const float4* feats = (const float4*)d_in[1];
    const int*    rnds  = (const int*)d_in[2];
    float*        out   = (float*)d_out;
    (void)in_sizes; (void)n_in; (void)out_size;

    init_kernel<<<(2 * BATCH * NC + 255) / 256, 256>>>();

    const int total = BATCH * HALF * 8 + 2 * BATCH * HALF + NPTS;  // 344064
    gather_kernel<<<total / 256, 256>>>(pc, feats, rnds, out);

    scan_kernel<<<2 * BATCH, 1024>>>();
    scatter_kernel<<<(2 * BATCH * HALF + 255) / 256, 256>>>();

    knn_kernel<<<BATCH * HALF * 32 / 256, 256>>>(out);
}